// round 1
// baseline (speedup 1.0000x reference)
#include <cuda_runtime.h>

#define EPS 1e-6f

// Scratch (device globals: no allocation allowed)
__device__ float g_xr[256*128*64];          // normalized xr, 8 MB
__device__ float g_coef[128*64*64];         // coef[n][k][j], 2 MB
__device__ __align__(16) unsigned char g_itab[64*64]; // i index per (k,j)
__device__ float g_sgn[64*64];              // cayley sign per (k,j)

// ---------------------------------------------------------------------------
// Setup A: for each (j,k) find the unique i with cayley[i,j,k] != 0.
__global__ void k_setup_tab(const float* __restrict__ cayley) {
    int j = blockIdx.x, k = threadIdx.x;
    int ii = 0; float s = 0.f;
    #pragma unroll 8
    for (int i = 0; i < 64; i++) {
        float v = cayley[i*4096 + j*64 + k];
        if (v != 0.f) { ii = i; s = v; }
    }
    g_itab[k*64 + j] = (unsigned char)ii;
    g_sgn[k*64 + j]  = s;
}

// Setup B: per n, scatter w_gp into full4[4][4][4], then build
// coef[n][k][j] = sign(j,k) * full4[cls[i(j,k)]][cls[j]][cls[k]].
__global__ void k_setup_coef(const float* __restrict__ w_gp,
                             const int* __restrict__ cls,
                             const int* __restrict__ pidx, int P) {
    __shared__ float f4[64];
    __shared__ int scls[64];
    int n = blockIdx.x, t = threadIdx.x;
    if (t < 64) { f4[t] = 0.f; scls[t] = cls[t]; }
    __syncthreads();
    for (int p = t; p < P; p += 256) {
        int code = pidx[3*p]*16 + pidx[3*p+1]*4 + pidx[3*p+2];
        f4[code] = w_gp[n*P + p];
    }
    __syncthreads();
    #pragma unroll
    for (int r = 0; r < 16; r++) {
        int idx = t + 256*r;              // idx = k*64 + j
        int k = idx >> 6, j = idx & 63;
        int i = g_itab[idx];
        int code = scls[i]*16 + scls[j]*4 + scls[k];
        g_coef[n*4096 + idx] = g_sgn[idx] * f4[code];
    }
}

// ---------------------------------------------------------------------------
// Kernel 1: xr = class-gathered linear mix + bias(blade0) + class-norm gate.
// grid 2048 = (b:256) x (ntile:8 of 16 n), block 256 = 8 warps.
// Warp w handles n = base+w and base+w+8; lane = blade i0, also blade i0+32.
__global__ void k_linear(const float* __restrict__ x,
                         const float* __restrict__ w_lin,
                         const float* __restrict__ b_lin,
                         const float* __restrict__ a_norm,
                         const int* __restrict__ cls) {
    extern __shared__ float sm[];
    float* Xs = sm;            // [128 m][64 i]   8192 floats
    float* Ws = sm + 8192;     // [16 n][128 m][4 c] 8192 floats
    __shared__ int scls[64];
    int t = threadIdx.x;
    int b = blockIdx.x >> 3, nt = blockIdx.x & 7;
    if (t < 64) scls[t] = cls[t];

    const float4* xg = (const float4*)(x + (size_t)b*8192);
    const float4* wg = (const float4*)(w_lin + nt*8192);
    float4* xs4 = (float4*)Xs; float4* ws4 = (float4*)Ws;
    #pragma unroll
    for (int r = 0; r < 8; r++) {
        xs4[t + 256*r] = xg[t + 256*r];
        ws4[t + 256*r] = wg[t + 256*r];
    }
    __syncthreads();

    int lane = t & 31, w = t >> 5;
    int i0 = lane, i1 = lane + 32;
    int c0 = scls[i0], c1 = scls[i1];
    float a00=0.f, a01=0.f, a10=0.f, a11=0.f;
    const float* W0 = Ws + w*512;
    const float* W1 = Ws + (w+8)*512;
    #pragma unroll 8
    for (int m = 0; m < 128; m++) {
        float xv0 = Xs[m*64 + i0];
        float xv1 = Xs[m*64 + i1];
        a00 = fmaf(xv0, W0[m*4+c0], a00);
        a01 = fmaf(xv1, W0[m*4+c1], a01);
        a10 = fmaf(xv0, W1[m*4+c0], a10);
        a11 = fmaf(xv1, W1[m*4+c1], a11);
    }
    int n0 = nt*16 + w, n1 = n0 + 8;
    if (lane == 0) { a00 += b_lin[n0]; a10 += b_lin[n1]; }

    // per-class squared sums over all 64 blades (warp owns them all)
    float v0[4], v1[4];
    #pragma unroll
    for (int c = 0; c < 4; c++) {
        v0[c] = (c0==c ? a00*a00 : 0.f) + (c1==c ? a01*a01 : 0.f);
        v1[c] = (c0==c ? a10*a10 : 0.f) + (c1==c ? a11*a11 : 0.f);
    }
    #pragma unroll
    for (int off = 16; off; off >>= 1) {
        #pragma unroll
        for (int c = 0; c < 4; c++) {
            v0[c] += __shfl_xor_sync(0xffffffffu, v0[c], off);
            v1[c] += __shfl_xor_sync(0xffffffffu, v1[c], off);
        }
    }
    float d0[4], d1[4];
    #pragma unroll
    for (int c = 0; c < 4; c++) {
        float s0 = 1.f/(1.f + expf(-a_norm[n0*4+c]));
        float s1 = 1.f/(1.f + expf(-a_norm[n1*4+c]));
        d0[c] = s0*(sqrtf(v0[c]) - 1.f) + 1.f + EPS;
        d1[c] = s1*(sqrtf(v1[c]) - 1.f) + 1.f + EPS;
    }
    float den00 = (c0==0)?d0[0]:(c0==1)?d0[1]:(c0==2)?d0[2]:d0[3];
    float den01 = (c1==0)?d0[0]:(c1==1)?d0[1]:(c1==2)?d0[2]:d0[3];
    float den10 = (c0==0)?d1[0]:(c0==1)?d1[1]:(c0==2)?d1[2]:d1[3];
    float den11 = (c1==0)?d1[0]:(c1==1)?d1[1]:(c1==2)?d1[2]:d1[3];

    float* xo0 = g_xr + (size_t)b*8192 + n0*64;
    float* xo1 = g_xr + (size_t)b*8192 + n1*64;
    xo0[i0] = a00/den00; xo0[i1] = a01/den01;
    xo1[i0] = a10/den10; xo1[i1] = a11/den11;
}

// ---------------------------------------------------------------------------
// Kernel 2: out[b,n,j] = sum_k coef[n][k][j] * x[b,n,i(j,k)] * xr[b,n,k]
// grid (n:128, bg:4 of 64 b), block 256 = 8 warps.
// lane -> batches (2*lane, 2*lane+1); warp w -> j in [8w, 8w+8).
__global__ void k_bilinear(const float* __restrict__ x, float* __restrict__ out) {
    extern __shared__ float sm[];
    float* Cs = sm;               // coef[k][j]  4096 floats
    float* Xs = sm + 4096;        // [i][b] stride 66, 4224 floats
    float* Rs = Xs + 64*66;       // [k][b] stride 66, 4224 floats
    __shared__ unsigned int Is[1024];  // packed itab (4 bytes/word)
    int n = blockIdx.x, bg = blockIdx.y;
    int t = threadIdx.x;

    const float4* cg = (const float4*)(g_coef + n*4096);
    float4* cs4 = (float4*)Cs;
    #pragma unroll
    for (int r = 0; r < 4; r++) cs4[t + 256*r] = cg[t + 256*r];
    const unsigned int* ig = (const unsigned int*)g_itab;
    #pragma unroll
    for (int r = 0; r < 4; r++) Is[t + 256*r] = ig[t + 256*r];
    #pragma unroll
    for (int r = 0; r < 16; r++) {
        int idx = t + 256*r;
        int bl = idx >> 6, i = idx & 63;
        size_t go = (size_t)(bg*64 + bl)*8192 + (size_t)n*64 + i;
        Xs[i*66 + bl] = x[go];
        Rs[i*66 + bl] = g_xr[go];
    }
    __syncthreads();

    int lane = t & 31, w = t >> 5;
    float ax[8], ay[8];
    #pragma unroll
    for (int jj = 0; jj < 8; jj++) { ax[jj] = 0.f; ay[jj] = 0.f; }

    for (int k = 0; k < 64; k++) {
        float2 r2 = *(const float2*)(Rs + k*66 + 2*lane);  // conflict-free
        unsigned int p0 = Is[k*16 + 2*w];                  // broadcast
        unsigned int p1 = Is[k*16 + 2*w + 1];
        const float* Ck = Cs + k*64 + w*8;
        #pragma unroll
        for (int jj = 0; jj < 8; jj++) {
            unsigned int p = (jj < 4) ? p0 : p1;
            int i = (p >> ((jj & 3)*8)) & 0xff;
            float c = Ck[jj];                              // broadcast
            float2 xv = *(const float2*)(Xs + i*66 + 2*lane); // conflict-free
            ax[jj] = fmaf(c, xv.x * r2.x, ax[jj]);
            ay[jj] = fmaf(c, xv.y * r2.y, ay[jj]);
        }
    }
    __syncthreads();
    // stage to smem so the global write is coalesced 256B rows
    #pragma unroll
    for (int jj = 0; jj < 8; jj++) {
        Xs[(2*lane  )*66 + w*8 + jj] = ax[jj];
        Xs[(2*lane+1)*66 + w*8 + jj] = ay[jj];
    }
    __syncthreads();
    #pragma unroll
    for (int r = 0; r < 16; r++) {
        int idx = t + 256*r;
        int bl = idx >> 6, j = idx & 63;
        out[(size_t)(bg*64 + bl)*8192 + (size_t)n*64 + j] = Xs[bl*66 + j];
    }
}

// ---------------------------------------------------------------------------
extern "C" void kernel_launch(void* const* d_in, const int* in_sizes, int n_in,
                              void* d_out, int out_size) {
    const float* x      = (const float*)d_in[0];
    const float* w_gp   = (const float*)d_in[1];
    const float* w_lin  = (const float*)d_in[2];
    const float* b_lin  = (const float*)d_in[3];
    const float* a_norm = (const float*)d_in[4];
    const float* cayley = (const float*)d_in[5];
    const int*   cls    = (const int*)d_in[6];
    const int*   pidx   = (const int*)d_in[7];
    int P = in_sizes[7] / 3;
    float* out = (float*)d_out;

    (void)n_in; (void)out_size;

    cudaFuncSetAttribute(k_linear,  cudaFuncAttributeMaxDynamicSharedMemorySize, 66*1024);
    cudaFuncSetAttribute(k_bilinear, cudaFuncAttributeMaxDynamicSharedMemorySize, 52*1024);

    k_setup_tab<<<64, 64>>>(cayley);
    k_setup_coef<<<128, 256>>>(w_gp, cls, pidx, P);
    k_linear<<<2048, 256, 16384*4>>>(x, w_lin, b_lin, a_norm, cls);
    k_bilinear<<<dim3(128, 4), 256, (4096 + 2*64*66)*4>>>(x, out);
}

// round 2
// speedup vs baseline: 1.1058x; 1.1058x over previous
#include <cuda_runtime.h>

#define EPS 1e-6f

// Scratch (device globals: no allocation allowed)
__device__ float g_xr[256*128*64];     // xr in BINARY blade order, 8 MB
__device__ float g_coef[128*64*64];    // coef[n][k_bin][j_bin], 2 MB
__device__ float g_sgnb[64*64];        // cayley sign per (k_bin,j_bin)
__device__ int   g_b2s[64];            // binary blade -> sorted index
__device__ int   g_s2c[64];            // sorted index -> class-order pos
__device__ int   g_c2b[64];            // class-order pos -> binary blade
__device__ int   g_qcls[16];           // class per class-order quad

// ---------------------------------------------------------------------------
// Setup A: orderings + sign table in binary order (i = j ^ k).
__global__ void k_setup_tables(const float* __restrict__ cayley) {
    __shared__ int s_of_b[64];
    int t = threadIdx.x;
    if (t < 64) {
        int pc = __popc(t);
        int rank = 0;
        for (int u = 0; u < 64; u++) {
            int pu = __popc(u);
            rank += (pu < pc) || (pu == pc && u < t);
        }
        s_of_b[t] = rank;
        g_b2s[t] = rank;
    }
    __syncthreads();
    if (t < 64) {
        int c = __popc(t) & 3;
        int s = s_of_b[t];
        int co = 0;
        for (int u = 0; u < 64; u++) {
            int cu = __popc(u) & 3;
            co += (cu < c) || (cu == c && s_of_b[u] < s);
        }
        g_s2c[s] = co;
        g_c2b[co] = t;
        if ((co & 3) == 0) g_qcls[co >> 2] = c;
    }
    __syncthreads();
    #pragma unroll
    for (int r = 0; r < 16; r++) {
        int idx = t + 256*r;                 // idx = k*64 + j (binary)
        int k = idx >> 6, j = idx & 63;
        int i = j ^ k;
        g_sgnb[idx] = cayley[s_of_b[i]*4096 + s_of_b[j]*64 + s_of_b[k]];
    }
}

// Setup B: per n, coef[k_bin][j_bin] = sgn * f4[cls(i)][cls(j)][cls(k)].
__global__ void k_setup_coef(const float* __restrict__ w_gp,
                             const int* __restrict__ pidx, int P) {
    __shared__ float f4[64];
    int n = blockIdx.x, t = threadIdx.x;
    if (t < 64) f4[t] = 0.f;
    __syncthreads();
    for (int p = t; p < P; p += 256) {
        int code = pidx[3*p]*16 + pidx[3*p+1]*4 + pidx[3*p+2];
        f4[code] = w_gp[n*P + p];
    }
    __syncthreads();
    #pragma unroll
    for (int r = 0; r < 16; r++) {
        int idx = t + 256*r;
        int k = idx >> 6, j = idx & 63;
        int i = j ^ k;
        int code = (__popc(i)&3)*16 + (__popc(j)&3)*4 + (__popc(k)&3);
        g_coef[n*4096 + idx] = g_sgnb[idx] * f4[code];
    }
}

// ---------------------------------------------------------------------------
// Kernel 1: linear mix + bias + class-norm gate. Blades class-sorted so each
// thread's 4 blades share one weight scalar. Output written in BINARY order.
// grid 1024 = (b:256) x (nt:4 of 32 n), block 256.
// thread: ig = quad of class-ordered blades (16), nh = n slot (16); handles
// n0 = nt*32+nh and n1 = n0+16.
__global__ __launch_bounds__(256, 2) void k_linear(
    const float* __restrict__ x, const float* __restrict__ w_lin,
    const float* __restrict__ b_lin, const float* __restrict__ a_norm) {
    extern __shared__ float sm[];
    float* Xs = sm;           // [128 m][64 co]  32 KB
    float* Ws = sm + 8192;    // [128 m][pad 160: nl*5+c]  80 KB
    __shared__ int ss2c[64], sc2b[64], sq[16];
    int t = threadIdx.x;
    int b = blockIdx.x >> 2, nt = blockIdx.x & 3;
    if (t < 64) { ss2c[t] = g_s2c[t]; sc2b[t] = g_c2b[t]; }
    if (t < 16) sq[t] = g_qcls[t];
    __syncthreads();

    const float* xrow = x + (size_t)b*8192;
    #pragma unroll
    for (int r = 0; r < 32; r++) {
        int idx = t + 256*r;
        int m = idx >> 6, s = idx & 63;
        Xs[m*64 + ss2c[s]] = xrow[idx];
    }
    const float* wbase = w_lin + nt*32*512;
    #pragma unroll
    for (int r = 0; r < 64; r++) {
        int idx = t + 256*r;
        int nl = idx >> 9, rem = idx & 511;
        int m = rem >> 2, c = rem & 3;
        Ws[m*160 + nl*5 + c] = wbase[idx];
    }
    __syncthreads();

    int ig = t & 15, nh = t >> 4;
    int c = sq[ig];
    int off0 = nh*5 + c, off1 = off0 + 80;
    const float4* Xs4 = (const float4*)Xs;
    float4 a0 = {0,0,0,0}, a1 = {0,0,0,0};
    #pragma unroll 8
    for (int m = 0; m < 128; m++) {
        float4 xq = Xs4[m*16 + ig];
        float w0 = Ws[m*160 + off0];
        float w1 = Ws[m*160 + off1];
        a0.x = fmaf(xq.x, w0, a0.x); a0.y = fmaf(xq.y, w0, a0.y);
        a0.z = fmaf(xq.z, w0, a0.z); a0.w = fmaf(xq.w, w0, a0.w);
        a1.x = fmaf(xq.x, w1, a1.x); a1.y = fmaf(xq.y, w1, a1.y);
        a1.z = fmaf(xq.z, w1, a1.z); a1.w = fmaf(xq.w, w1, a1.w);
    }
    int n0 = nt*32 + nh, n1 = n0 + 16;
    if (ig == 0) { a0.x += b_lin[n0]; a1.x += b_lin[n1]; }

    float s0 = a0.x*a0.x + a0.y*a0.y + a0.z*a0.z + a0.w*a0.w;
    float s1 = a1.x*a1.x + a1.y*a1.y + a1.z*a1.z + a1.w*a1.w;
    float v0[4], v1[4];
    #pragma unroll
    for (int cc = 0; cc < 4; cc++) {
        v0[cc] = (c == cc) ? s0 : 0.f;
        v1[cc] = (c == cc) ? s1 : 0.f;
    }
    #pragma unroll
    for (int off = 8; off; off >>= 1) {
        #pragma unroll
        for (int cc = 0; cc < 4; cc++) {
            v0[cc] += __shfl_xor_sync(0xffffffffu, v0[cc], off);
            v1[cc] += __shfl_xor_sync(0xffffffffu, v1[cc], off);
        }
    }
    float vv0 = (c==0)?v0[0]:(c==1)?v0[1]:(c==2)?v0[2]:v0[3];
    float vv1 = (c==0)?v1[0]:(c==1)?v1[1]:(c==2)?v1[2]:v1[3];
    float gg0 = 1.f/(1.f + expf(-a_norm[n0*4 + c]));
    float gg1 = 1.f/(1.f + expf(-a_norm[n1*4 + c]));
    float inv0 = 1.f/(gg0*(sqrtf(vv0) - 1.f) + 1.f + EPS);
    float inv1 = 1.f/(gg1*(sqrtf(vv1) - 1.f) + 1.f + EPS);

    float* o0 = g_xr + (size_t)b*8192 + (size_t)n0*64;
    float* o1 = g_xr + (size_t)b*8192 + (size_t)n1*64;
    int co = ig*4;
    o0[sc2b[co+0]] = a0.x*inv0; o0[sc2b[co+1]] = a0.y*inv0;
    o0[sc2b[co+2]] = a0.z*inv0; o0[sc2b[co+3]] = a0.w*inv0;
    o1[sc2b[co+0]] = a1.x*inv1; o1[sc2b[co+1]] = a1.y*inv1;
    o1[sc2b[co+2]] = a1.z*inv1; o1[sc2b[co+3]] = a1.w*inv1;
}

// ---------------------------------------------------------------------------
// Kernel 2: out[b,n,j] = sum_k coef[n][k][j] * x[b,n,j^k] * xr[b,n,k]
// (binary blade order; i = j^k by XOR — no index table).
// grid (n:128, bg:2 of 128 b), block 128: one thread per (b,n) pair.
// x row held entirely in registers; both loops fully unrolled.
__global__ __launch_bounds__(128, 2) void k_bilinear(
    const float* __restrict__ x, float* __restrict__ out) {
    extern __shared__ float sm[];
    float* Cs = sm;                 // coef[k][j]          16 KB
    float* Rs = sm + 4096;          // xr rows [b][65]     33.3 KB
    float* Xt = Rs + 128*65;        // x rows  [b][65]     33.3 KB
    __shared__ int sj[64];
    int n = blockIdx.x, bg = blockIdx.y;
    int t = threadIdx.x;
    if (t < 64) sj[t] = g_b2s[t];

    float4* Cs4w = (float4*)Cs;
    const float4* cg = (const float4*)(g_coef + (size_t)n*4096);
    #pragma unroll
    for (int r = 0; r < 8; r++) Cs4w[t + 128*r] = cg[t + 128*r];

    int w = t >> 5, lane = t & 31;
    #pragma unroll
    for (int rr = 0; rr < 32; rr++) {
        int row = w*32 + rr;
        size_t go = (size_t)(bg*128 + row)*8192 + (size_t)n*64;
        Rs[row*65 + lane]      = g_xr[go + lane];
        Rs[row*65 + 32 + lane] = g_xr[go + 32 + lane];
        Xt[row*65 + lane]      = x[go + lane];
        Xt[row*65 + 32 + lane] = x[go + 32 + lane];
    }
    __syncthreads();

    float xv[64];
    #pragma unroll
    for (int i = 0; i < 64; i++) xv[i] = Xt[t*65 + sj[i]];  // binary order
    float acc[64];
    #pragma unroll
    for (int j = 0; j < 64; j++) acc[j] = 0.f;

    const float4* Cs4 = (const float4*)Cs;
    #pragma unroll
    for (int k = 0; k < 64; k++) {
        float rv = Rs[t*65 + k];
        #pragma unroll
        for (int q = 0; q < 16; q++) {
            float4 cq = Cs4[k*16 + q];
            int j0 = q*4;
            acc[j0+0] = fmaf(cq.x, xv[(j0+0)^k]*rv, acc[j0+0]);
            acc[j0+1] = fmaf(cq.y, xv[(j0+1)^k]*rv, acc[j0+1]);
            acc[j0+2] = fmaf(cq.z, xv[(j0+2)^k]*rv, acc[j0+2]);
            acc[j0+3] = fmaf(cq.w, xv[(j0+3)^k]*rv, acc[j0+3]);
        }
    }

    float* orow = out + (size_t)(bg*128 + t)*8192 + (size_t)n*64;
    #pragma unroll
    for (int j = 0; j < 64; j++) orow[sj[j]] = acc[j];
}

// ---------------------------------------------------------------------------
extern "C" void kernel_launch(void* const* d_in, const int* in_sizes, int n_in,
                              void* d_out, int out_size) {
    const float* x      = (const float*)d_in[0];
    const float* w_gp   = (const float*)d_in[1];
    const float* w_lin  = (const float*)d_in[2];
    const float* b_lin  = (const float*)d_in[3];
    const float* a_norm = (const float*)d_in[4];
    const float* cayley = (const float*)d_in[5];
    const int*   pidx   = (const int*)d_in[7];
    int P = in_sizes[7] / 3;
    float* out = (float*)d_out;
    (void)n_in; (void)out_size;

    cudaFuncSetAttribute(k_linear,   cudaFuncAttributeMaxDynamicSharedMemorySize, (8192 + 128*160)*4);
    cudaFuncSetAttribute(k_bilinear, cudaFuncAttributeMaxDynamicSharedMemorySize, (4096 + 2*128*65)*4);

    k_setup_tables<<<1, 256>>>(cayley);
    k_setup_coef<<<128, 256>>>(w_gp, pidx, P);
    k_linear<<<1024, 256, (8192 + 128*160)*4>>>(x, w_lin, b_lin, a_norm);
    k_bilinear<<<dim3(128, 2), 128, (4096 + 2*128*65)*4>>>(x, out);
}

// round 3
// speedup vs baseline: 1.3217x; 1.1953x over previous
#include <cuda_runtime.h>

#define EPS 1e-6f
typedef unsigned long long u64t;

#define MUL2(d,a,b)    asm("mul.rn.f32x2 %0, %1, %2;" : "=l"(d) : "l"(a), "l"(b))
#define FMA2(d,a,b,c)  asm("fma.rn.f32x2 %0, %1, %2, %3;" : "=l"(d) : "l"(a), "l"(b), "l"(c))
#define PACK2(d,lo,hi) asm("mov.b64 %0, {%1, %2};" : "=l"(d) : "f"(lo), "f"(hi))
#define UNPACK2(lo,hi,s) asm("mov.b64 {%0, %1}, %2;" : "=f"(lo), "=f"(hi) : "l"(s))
#define LDS64(d, addr)    asm volatile("ld.shared.b64 %0, [%1];" : "=l"(d) : "r"(addr))
#define LDS128(a, b, addr) asm volatile("ld.shared.v2.u64 {%0,%1}, [%2];" : "=l"(a), "=l"(b) : "r"(addr))

// Scratch (device globals: no allocation allowed)
__device__ float g_xr[256*128*64];     // xr in BINARY blade order, 8 MB
__device__ float g_coef[128*64*64];    // coef[n][k_bin][j_bin], 2 MB
__device__ float g_sgnb[64*64];        // cayley sign per (k_bin,j_bin)
__device__ int   g_b2s[64];            // binary blade -> sorted index
__device__ int   g_s2c[64];            // sorted index -> class-order pos
__device__ int   g_c2b[64];            // class-order pos -> binary blade
__device__ int   g_qcls[16];           // class per class-order quad

// ---------------------------------------------------------------------------
// Setup A: orderings + sign table in binary order (i = j ^ k). grid 16 x 256.
__global__ void k_setup_tables(const float* __restrict__ cayley) {
    __shared__ int s_of_b[64];
    int t = threadIdx.x;
    if (t < 64) {
        int pc = __popc(t);
        int rank = 0;
        for (int u = 0; u < 64; u++) {
            int pu = __popc(u);
            rank += (pu < pc) || (pu == pc && u < t);
        }
        s_of_b[t] = rank;
    }
    __syncthreads();
    if (blockIdx.x == 0 && t < 64) {
        g_b2s[t] = s_of_b[t];
        int c = __popc(t) & 3;
        int s = s_of_b[t];
        int co = 0;
        for (int u = 0; u < 64; u++) {
            int cu = __popc(u) & 3;
            co += (cu < c) || (cu == c && s_of_b[u] < s);
        }
        g_s2c[s] = co;
        g_c2b[co] = t;
        if ((co & 3) == 0) g_qcls[co >> 2] = c;
    }
    int idx = blockIdx.x*256 + t;            // idx = k*64 + j (binary)
    int k = idx >> 6, j = idx & 63, i = j ^ k;
    g_sgnb[idx] = cayley[s_of_b[i]*4096 + s_of_b[j]*64 + s_of_b[k]];
}

// Setup B: per n, coef[k_bin][j_bin] = sgn * f4[cls(i)][cls(j)][cls(k)].
__global__ void k_setup_coef(const float* __restrict__ w_gp,
                             const int* __restrict__ pidx, int P) {
    __shared__ float f4[64];
    int n = blockIdx.x, t = threadIdx.x;
    if (t < 64) f4[t] = 0.f;
    __syncthreads();
    for (int p = t; p < P; p += 256) {
        int code = pidx[3*p]*16 + pidx[3*p+1]*4 + pidx[3*p+2];
        f4[code] = w_gp[n*P + p];
    }
    __syncthreads();
    #pragma unroll
    for (int r = 0; r < 16; r++) {
        int idx = t + 256*r;
        int k = idx >> 6, j = idx & 63;
        int i = j ^ k;
        int code = (__popc(i)&3)*16 + (__popc(j)&3)*4 + (__popc(k)&3);
        g_coef[n*4096 + idx] = g_sgnb[idx] * f4[code];
    }
}

// ---------------------------------------------------------------------------
// Kernel 1: linear mix + bias + class-norm gate, f32x2 packed over m-pairs.
// grid 1024 = (b:256) x (nt:4 of 32 n), block 256.
// thread: ig = class-ordered blade quad (16), nh = n slot (16);
// handles n0 = nt*32+nh and n1 = n0+16.
// smem: Xp words [0, 8448): [64 mp][132]: pair(co) at mp*132 + co*2
//       Wp words [8448, 24960): [64 mp][258]: pair(slot,c) at mp*258+(slot*4+c)*2
__global__ __launch_bounds__(256, 2) void k_linear(
    const float* __restrict__ x, const float* __restrict__ w_lin,
    const float* __restrict__ b_lin, const float* __restrict__ a_norm) {
    extern __shared__ float sm[];
    __shared__ int ss2c[64], sc2b[64], sq[16];
    int t = threadIdx.x;
    int b = blockIdx.x >> 2, nt = blockIdx.x & 3;
    if (t < 64) { ss2c[t] = g_s2c[t]; sc2b[t] = g_c2b[t]; }
    if (t < 16) sq[t] = g_qcls[t];
    __syncthreads();

    const float* xrow = x + (size_t)b*8192;
    #pragma unroll
    for (int r = 0; r < 32; r++) {
        int idx = t + 256*r;
        int m = idx >> 6, s = idx & 63;
        int co = ss2c[s];
        sm[(m>>1)*132 + co*2 + (m&1)] = xrow[idx];
    }
    const float4* w4 = (const float4*)(w_lin + nt*32*512);
    #pragma unroll
    for (int r = 0; r < 16; r++) {
        int idx4 = t + 256*r;
        int slot = idx4 >> 7, m = idx4 & 127;
        float4 v = w4[idx4];
        int base = 8448 + (m>>1)*258 + slot*8 + (m&1);
        sm[base + 0] = v.x; sm[base + 2] = v.y;
        sm[base + 4] = v.z; sm[base + 6] = v.w;
    }
    __syncthreads();

    int ig = t & 15, nh = t >> 4;
    int c = sq[ig];
    unsigned sb = (unsigned)__cvta_generic_to_shared(sm);
    unsigned xbase  = sb + (unsigned)(ig*8)*4u;
    unsigned wbaseA = sb + (unsigned)(8448 + (nh*4 + c)*2)*4u;
    unsigned wbaseB = sb + (unsigned)(8448 + ((nh+16)*4 + c)*2)*4u;

    u64t a0q[4] = {0,0,0,0}, a1q[4] = {0,0,0,0};
    #pragma unroll 8
    for (int mp = 0; mp < 64; mp++) {
        u64t x0,x1,x2,x3, wA, wB;
        LDS128(x0, x1, xbase + mp*528u);
        LDS128(x2, x3, xbase + mp*528u + 16u);
        LDS64(wA, wbaseA + mp*1032u);
        LDS64(wB, wbaseB + mp*1032u);
        FMA2(a0q[0], x0, wA, a0q[0]);
        FMA2(a0q[1], x1, wA, a0q[1]);
        FMA2(a0q[2], x2, wA, a0q[2]);
        FMA2(a0q[3], x3, wA, a0q[3]);
        FMA2(a1q[0], x0, wB, a1q[0]);
        FMA2(a1q[1], x1, wB, a1q[1]);
        FMA2(a1q[2], x2, wB, a1q[2]);
        FMA2(a1q[3], x3, wB, a1q[3]);
    }
    float f0[4], f1[4];
    #pragma unroll
    for (int q = 0; q < 4; q++) {
        float lo, hi;
        UNPACK2(lo, hi, a0q[q]); f0[q] = lo + hi;
        UNPACK2(lo, hi, a1q[q]); f1[q] = lo + hi;
    }
    int n0 = nt*32 + nh, n1 = n0 + 16;
    if (ig == 0) { f0[0] += b_lin[n0]; f1[0] += b_lin[n1]; }

    float s0 = f0[0]*f0[0] + f0[1]*f0[1] + f0[2]*f0[2] + f0[3]*f0[3];
    float s1 = f1[0]*f1[0] + f1[1]*f1[1] + f1[2]*f1[2] + f1[3]*f1[3];
    float v0[4], v1[4];
    #pragma unroll
    for (int cc = 0; cc < 4; cc++) {
        v0[cc] = (c == cc) ? s0 : 0.f;
        v1[cc] = (c == cc) ? s1 : 0.f;
    }
    #pragma unroll
    for (int off = 8; off; off >>= 1) {
        #pragma unroll
        for (int cc = 0; cc < 4; cc++) {
            v0[cc] += __shfl_xor_sync(0xffffffffu, v0[cc], off);
            v1[cc] += __shfl_xor_sync(0xffffffffu, v1[cc], off);
        }
    }
    float vv0 = (c==0)?v0[0]:(c==1)?v0[1]:(c==2)?v0[2]:v0[3];
    float vv1 = (c==0)?v1[0]:(c==1)?v1[1]:(c==2)?v1[2]:v1[3];
    float gg0 = 1.f/(1.f + expf(-a_norm[n0*4 + c]));
    float gg1 = 1.f/(1.f + expf(-a_norm[n1*4 + c]));
    float inv0 = 1.f/(gg0*(sqrtf(vv0) - 1.f) + 1.f + EPS);
    float inv1 = 1.f/(gg1*(sqrtf(vv1) - 1.f) + 1.f + EPS);

    float* o0 = g_xr + (size_t)b*8192 + (size_t)n0*64;
    float* o1 = g_xr + (size_t)b*8192 + (size_t)n1*64;
    int co = ig*4;
    o0[sc2b[co+0]] = f0[0]*inv0; o0[sc2b[co+1]] = f0[1]*inv0;
    o0[sc2b[co+2]] = f0[2]*inv0; o0[sc2b[co+3]] = f0[3]*inv0;
    o1[sc2b[co+0]] = f1[0]*inv1; o1[sc2b[co+1]] = f1[1]*inv1;
    o1[sc2b[co+2]] = f1[2]*inv1; o1[sc2b[co+3]] = f1[3]*inv1;
}

// ---------------------------------------------------------------------------
// Kernel 2: out[b,n,j] = sum_k coef[n][k][j] * x[b,n,j^k] * xr[b,n,k]
// f32x2 packed over batch pairs. grid (n:128, bg:4), block 256.
// warp = j-octet jo; lane = batch pair bp (batches bg*64+2*lane, +1).
// k tiled in octets: i-octet = (jo^ko) octet, xv/rv held in regs per tile.
// smem words: Cs2 dup pairs [0, 8192); Rp [8192,12416): k*66+2*bp;
//             Xp [12416, 16640): i*66+2*bp.
__global__ __launch_bounds__(256, 3) void k_bilinear(
    const float* __restrict__ x, float* __restrict__ out) {
    extern __shared__ float sm[];
    __shared__ int sjb[64];
    int n = blockIdx.x, bg = blockIdx.y;
    int t = threadIdx.x;
    if (t < 64) sjb[t] = g_b2s[t];

    u64t* Cs2 = (u64t*)sm;
    #pragma unroll
    for (int r = 0; r < 16; r++) {
        int idx = t + 256*r;
        float c = g_coef[n*4096 + idx];
        u64t pc; PACK2(pc, c, c);
        Cs2[idx] = pc;
    }
    __syncthreads();   // sjb ready
    #pragma unroll
    for (int r = 0; r < 8; r++) {
        int p = t + 256*r;
        int i = p & 63, bq = p >> 6;
        size_t gb = (size_t)(bg*64 + 2*bq)*8192 + (size_t)n*64;
        int s = sjb[i];
        float xl = x[gb + s],      xh = x[gb + 8192 + s];
        float rl = g_xr[gb + i],   rh = g_xr[gb + 8192 + i];
        u64t px, pr; PACK2(px, xl, xh); PACK2(pr, rl, rh);
        *(u64t*)(sm + 12416 + i*66 + 2*bq) = px;
        *(u64t*)(sm + 8192  + i*66 + 2*bq) = pr;
    }
    __syncthreads();

    int lane = t & 31, jo = t >> 5;
    unsigned sb = (unsigned)__cvta_generic_to_shared(sm);
    unsigned sC = sb + (unsigned)(jo*8)*8u;
    unsigned sR = sb + (unsigned)(8192  + 2*lane)*4u;
    unsigned sX = sb + (unsigned)(12416 + 2*lane)*4u;

    u64t acc[8];
    #pragma unroll
    for (int jj = 0; jj < 8; jj++) acc[jj] = 0ull;

    for (int ko = 0; ko < 8; ko++) {
        u64t rv[8], xv[8];
        unsigned rb = sR + (unsigned)(ko*8)*264u;
        #pragma unroll
        for (int kk = 0; kk < 8; kk++) LDS64(rv[kk], rb + kk*264u);
        unsigned xb = sX + (unsigned)((jo ^ ko)*8)*264u;
        #pragma unroll
        for (int d = 0; d < 8; d++) LDS64(xv[d], xb + d*264u);
        unsigned cb = sC + (unsigned)ko*4096u;
        #pragma unroll
        for (int kk = 0; kk < 8; kk++) {
            #pragma unroll
            for (int jj = 0; jj < 8; jj++) {
                u64t c2, tm;
                LDS64(c2, cb + (unsigned)(kk*64 + jj)*8u);
                MUL2(tm, xv[jj^kk], rv[kk]);
                FMA2(acc[jj], c2, tm, acc[jj]);
            }
        }
    }
    __syncthreads();
    float* Os = sm;   // 64 rows x 68 floats, reuses Cs2 region
    #pragma unroll
    for (int jj = 0; jj < 8; jj++) {
        float lo, hi; UNPACK2(lo, hi, acc[jj]);
        int sjq = sjb[jo*8 + jj];
        Os[(2*lane)*68 + sjq]   = lo;
        Os[(2*lane+1)*68 + sjq] = hi;
    }
    __syncthreads();
    #pragma unroll
    for (int r = 0; r < 4; r++) {
        int idx = t + 256*r;
        int row = idx >> 4, c4 = idx & 15;
        float4 v = *(const float4*)(Os + row*68 + c4*4);
        *(float4*)(out + (size_t)(bg*64 + row)*8192 + (size_t)n*64 + c4*4) = v;
    }
}

// ---------------------------------------------------------------------------
extern "C" void kernel_launch(void* const* d_in, const int* in_sizes, int n_in,
                              void* d_out, int out_size) {
    const float* x      = (const float*)d_in[0];
    const float* w_gp   = (const float*)d_in[1];
    const float* w_lin  = (const float*)d_in[2];
    const float* b_lin  = (const float*)d_in[3];
    const float* a_norm = (const float*)d_in[4];
    const float* cayley = (const float*)d_in[5];
    const int*   pidx   = (const int*)d_in[7];
    int P = in_sizes[7] / 3;
    float* out = (float*)d_out;
    (void)n_in; (void)out_size;

    cudaFuncSetAttribute(k_linear,   cudaFuncAttributeMaxDynamicSharedMemorySize, 24960*4);
    cudaFuncSetAttribute(k_bilinear, cudaFuncAttributeMaxDynamicSharedMemorySize, 16640*4);

    k_setup_tables<<<16, 256>>>(cayley);
    k_setup_coef<<<128, 256>>>(w_gp, pidx, P);
    k_linear<<<1024, 256, 24960*4>>>(x, w_lin, b_lin, a_norm);
    k_bilinear<<<dim3(128, 4), 256, 16640*4>>>(x, out);
}

// round 4
// speedup vs baseline: 1.5235x; 1.1526x over previous
#include <cuda_runtime.h>

#define EPS 1e-6f
typedef unsigned long long u64t;

#define MUL2(d,a,b)    asm("mul.rn.f32x2 %0, %1, %2;" : "=l"(d) : "l"(a), "l"(b))
#define FMA2(d,a,b,c)  asm("fma.rn.f32x2 %0, %1, %2, %3;" : "=l"(d) : "l"(a), "l"(b), "l"(c))
#define PACK2(d,lo,hi) asm("mov.b64 %0, {%1, %2};" : "=l"(d) : "f"(lo), "f"(hi))
#define UNPACK2(lo,hi,s) asm("mov.b64 {%0, %1}, %2;" : "=f"(lo), "=f"(hi) : "l"(s))
#define LDS64(d, addr)    asm volatile("ld.shared.b64 %0, [%1];" : "=l"(d) : "r"(addr))
#define LDS128(a, b, addr) asm volatile("ld.shared.v2.u64 {%0,%1}, [%2];" : "=l"(a), "=l"(b) : "r"(addr))

// Scratch (device globals: no allocation allowed)
__device__ float g_xr[256*128*64];     // xr in BINARY blade order, 8 MB
__device__ float g_coef[128*64*64];    // coef[n][k_bin][j_bin], 2 MB
__device__ float g_sgnb[64*64];        // cayley sign per (k_bin,j_bin)
__device__ int   g_b2s[64];            // binary blade -> sorted index
__device__ int   g_s2c[64];            // sorted index -> class-order pos
__device__ int   g_c2b[64];            // class-order pos -> binary blade
__device__ int   g_qcls[16];           // class per class-order quad

// ---------------------------------------------------------------------------
// Setup A: orderings + sign table in binary order (i = j ^ k). grid 16 x 256.
__global__ void k_setup_tables(const float* __restrict__ cayley) {
    __shared__ int s_of_b[64];
    int t = threadIdx.x;
    if (t < 64) {
        int pc = __popc(t);
        int rank = 0;
        for (int u = 0; u < 64; u++) {
            int pu = __popc(u);
            rank += (pu < pc) || (pu == pc && u < t);
        }
        s_of_b[t] = rank;
    }
    __syncthreads();
    if (blockIdx.x == 0 && t < 64) {
        g_b2s[t] = s_of_b[t];
        int c = __popc(t) & 3;
        int s = s_of_b[t];
        int co = 0;
        for (int u = 0; u < 64; u++) {
            int cu = __popc(u) & 3;
            co += (cu < c) || (cu == c && s_of_b[u] < s);
        }
        g_s2c[s] = co;
        g_c2b[co] = t;
        if ((co & 3) == 0) g_qcls[co >> 2] = c;
    }
    int idx = blockIdx.x*256 + t;            // idx = k*64 + j (binary)
    int k = idx >> 6, j = idx & 63, i = j ^ k;
    g_sgnb[idx] = cayley[s_of_b[i]*4096 + s_of_b[j]*64 + s_of_b[k]];
}

// Setup B: per n, coef[k_bin][j_bin] = sgn * f4[cls(i)][cls(j)][cls(k)].
__global__ void k_setup_coef(const float* __restrict__ w_gp,
                             const int* __restrict__ pidx, int P) {
    __shared__ float f4[64];
    int n = blockIdx.x, t = threadIdx.x;
    if (t < 64) f4[t] = 0.f;
    __syncthreads();
    for (int p = t; p < P; p += 256) {
        int code = pidx[3*p]*16 + pidx[3*p+1]*4 + pidx[3*p+2];
        f4[code] = w_gp[n*P + p];
    }
    __syncthreads();
    #pragma unroll
    for (int r = 0; r < 16; r++) {
        int idx = t + 256*r;
        int k = idx >> 6, j = idx & 63;
        int i = j ^ k;
        int code = (__popc(i)&3)*16 + (__popc(j)&3)*4 + (__popc(k)&3);
        g_coef[n*4096 + idx] = g_sgnb[idx] * f4[code];
    }
}

// ---------------------------------------------------------------------------
// Kernel 1: linear mix + bias + class-norm gate, f32x2 packed over m-pairs.
// grid 1024 = (b:256) x (nt:4 of 32 n), block 256.
// thread: ig = class-ordered blade quad (16), nh = n slot (16);
// handles n0 = nt*32+nh and n1 = n0+16.
// smem: Xp words [0, 8960): [64 mp][140]: pair(co) at
//       mp*140 + co*2 + parity + (co>>4)*4  (pad-swizzle: conflict-free reads)
//       Wp words [8960, 25472): [64 mp][258]: pair(slot,c) at mp*258+(slot*4+c)*2
__global__ __launch_bounds__(256, 2) void k_linear(
    const float* __restrict__ x, const float* __restrict__ w_lin,
    const float* __restrict__ b_lin, const float* __restrict__ a_norm) {
    extern __shared__ float sm[];
    __shared__ int ss2c[64], sc2b[64], sq[16];
    int t = threadIdx.x;
    int b = blockIdx.x >> 2, nt = blockIdx.x & 3;
    if (t < 64) { ss2c[t] = g_s2c[t]; sc2b[t] = g_c2b[t]; }
    if (t < 16) sq[t] = g_qcls[t];
    __syncthreads();

    const float* xrow = x + (size_t)b*8192;
    #pragma unroll
    for (int r = 0; r < 32; r++) {
        int idx = t + 256*r;
        int m = idx >> 6, s = idx & 63;
        int co = ss2c[s];
        sm[(m>>1)*140 + co*2 + (m&1) + ((co>>4)<<2)] = xrow[idx];
    }
    const float4* w4 = (const float4*)(w_lin + nt*32*512);
    #pragma unroll
    for (int r = 0; r < 16; r++) {
        int idx4 = t + 256*r;
        int slot = idx4 >> 7, m = idx4 & 127;
        float4 v = w4[idx4];
        int base = 8960 + (m>>1)*258 + slot*8 + (m&1);
        sm[base + 0] = v.x; sm[base + 2] = v.y;
        sm[base + 4] = v.z; sm[base + 6] = v.w;
    }
    __syncthreads();

    int ig = t & 15, nh = t >> 4;
    int c = sq[ig];
    unsigned sb = (unsigned)__cvta_generic_to_shared(sm);
    unsigned xbase  = sb + (unsigned)(ig*8 + (ig>>2)*4)*4u;
    unsigned wbaseA = sb + (unsigned)(8960 + (nh*4 + c)*2)*4u;
    unsigned wbaseB = sb + (unsigned)(8960 + ((nh+16)*4 + c)*2)*4u;

    u64t a0q[4] = {0,0,0,0}, a1q[4] = {0,0,0,0};
    #pragma unroll 8
    for (int mp = 0; mp < 64; mp++) {
        u64t x0,x1,x2,x3, wA, wB;
        LDS128(x0, x1, xbase + mp*560u);
        LDS128(x2, x3, xbase + mp*560u + 16u);
        LDS64(wA, wbaseA + mp*1032u);
        LDS64(wB, wbaseB + mp*1032u);
        FMA2(a0q[0], x0, wA, a0q[0]);
        FMA2(a0q[1], x1, wA, a0q[1]);
        FMA2(a0q[2], x2, wA, a0q[2]);
        FMA2(a0q[3], x3, wA, a0q[3]);
        FMA2(a1q[0], x0, wB, a1q[0]);
        FMA2(a1q[1], x1, wB, a1q[1]);
        FMA2(a1q[2], x2, wB, a1q[2]);
        FMA2(a1q[3], x3, wB, a1q[3]);
    }
    float f0[4], f1[4];
    #pragma unroll
    for (int q = 0; q < 4; q++) {
        float lo, hi;
        UNPACK2(lo, hi, a0q[q]); f0[q] = lo + hi;
        UNPACK2(lo, hi, a1q[q]); f1[q] = lo + hi;
    }
    int n0 = nt*32 + nh, n1 = n0 + 16;
    if (ig == 0) { f0[0] += b_lin[n0]; f1[0] += b_lin[n1]; }

    float s0 = f0[0]*f0[0] + f0[1]*f0[1] + f0[2]*f0[2] + f0[3]*f0[3];
    float s1 = f1[0]*f1[0] + f1[1]*f1[1] + f1[2]*f1[2] + f1[3]*f1[3];
    float v0[4], v1[4];
    #pragma unroll
    for (int cc = 0; cc < 4; cc++) {
        v0[cc] = (c == cc) ? s0 : 0.f;
        v1[cc] = (c == cc) ? s1 : 0.f;
    }
    #pragma unroll
    for (int off = 8; off; off >>= 1) {
        #pragma unroll
        for (int cc = 0; cc < 4; cc++) {
            v0[cc] += __shfl_xor_sync(0xffffffffu, v0[cc], off);
            v1[cc] += __shfl_xor_sync(0xffffffffu, v1[cc], off);
        }
    }
    float vv0 = (c==0)?v0[0]:(c==1)?v0[1]:(c==2)?v0[2]:v0[3];
    float vv1 = (c==0)?v1[0]:(c==1)?v1[1]:(c==2)?v1[2]:v1[3];
    float gg0 = 1.f/(1.f + expf(-a_norm[n0*4 + c]));
    float gg1 = 1.f/(1.f + expf(-a_norm[n1*4 + c]));
    float inv0 = 1.f/(gg0*(sqrtf(vv0) - 1.f) + 1.f + EPS);
    float inv1 = 1.f/(gg1*(sqrtf(vv1) - 1.f) + 1.f + EPS);

    float* o0 = g_xr + (size_t)b*8192 + (size_t)n0*64;
    float* o1 = g_xr + (size_t)b*8192 + (size_t)n1*64;
    int co = ig*4;
    o0[sc2b[co+0]] = f0[0]*inv0; o0[sc2b[co+1]] = f0[1]*inv0;
    o0[sc2b[co+2]] = f0[2]*inv0; o0[sc2b[co+3]] = f0[3]*inv0;
    o1[sc2b[co+0]] = f1[0]*inv1; o1[sc2b[co+1]] = f1[1]*inv1;
    o1[sc2b[co+2]] = f1[2]*inv1; o1[sc2b[co+3]] = f1[3]*inv1;
}

// ---------------------------------------------------------------------------
// Kernel 2: out[b,n,j] = sum_k coef[n][k][j] * x[b,n,j^k] * xr[b,n,k]
// f32x2 packed over batch pairs. grid (n:128, bg:4), block 256.
// warp = j-octet jo; lane = batch pair bp.
// k tiled in octets: i-octet = (jo^ko) octet, xv/rv held in regs per tile.
// C stored as duplicated pairs, read 2 j's per LDS.128 (broadcast, 1 cyc).
// smem words: Cs2 dup pairs [0, 8192); Rp [8192,12416): k*66+2*bp;
//             Xp [12416, 16640): i*66+2*bp.
__global__ __launch_bounds__(256, 3) void k_bilinear(
    const float* __restrict__ x, float* __restrict__ out) {
    extern __shared__ float sm[];
    __shared__ int sjb[64];
    int n = blockIdx.x, bg = blockIdx.y;
    int t = threadIdx.x;
    if (t < 64) sjb[t] = g_b2s[t];

    u64t* Cs2 = (u64t*)sm;
    #pragma unroll
    for (int r = 0; r < 16; r++) {
        int idx = t + 256*r;
        float c = g_coef[n*4096 + idx];
        u64t pc; PACK2(pc, c, c);
        Cs2[idx] = pc;
    }
    __syncthreads();   // sjb ready
    #pragma unroll
    for (int r = 0; r < 8; r++) {
        int p = t + 256*r;
        int i = p & 63, bq = p >> 6;
        size_t gb = (size_t)(bg*64 + 2*bq)*8192 + (size_t)n*64;
        int s = sjb[i];
        float xl = x[gb + s],      xh = x[gb + 8192 + s];
        float rl = g_xr[gb + i],   rh = g_xr[gb + 8192 + i];
        u64t px, pr; PACK2(px, xl, xh); PACK2(pr, rl, rh);
        *(u64t*)(sm + 12416 + i*66 + 2*bq) = px;
        *(u64t*)(sm + 8192  + i*66 + 2*bq) = pr;
    }
    __syncthreads();

    int lane = t & 31, jo = t >> 5;
    unsigned sb = (unsigned)__cvta_generic_to_shared(sm);
    unsigned sC = sb + (unsigned)(jo*8)*8u;
    unsigned sR = sb + (unsigned)(8192  + 2*lane)*4u;
    unsigned sX = sb + (unsigned)(12416 + 2*lane)*4u;

    u64t acc[8];
    #pragma unroll
    for (int jj = 0; jj < 8; jj++) acc[jj] = 0ull;

    for (int ko = 0; ko < 8; ko++) {
        u64t rv[8], xv[8];
        unsigned rb = sR + (unsigned)(ko*8)*264u;
        #pragma unroll
        for (int kk = 0; kk < 8; kk++) LDS64(rv[kk], rb + kk*264u);
        unsigned xb = sX + (unsigned)((jo ^ ko)*8)*264u;
        #pragma unroll
        for (int d = 0; d < 8; d++) LDS64(xv[d], xb + d*264u);
        unsigned cb = sC + (unsigned)ko*4096u;
        #pragma unroll
        for (int kk = 0; kk < 8; kk++) {
            unsigned base2 = cb + (unsigned)kk*512u;
            #pragma unroll
            for (int jp = 0; jp < 4; jp++) {
                u64t cA, cB, t0, t1;
                LDS128(cA, cB, base2 + (unsigned)jp*16u);
                MUL2(t0, xv[(2*jp)^kk], rv[kk]);
                FMA2(acc[2*jp], cA, t0, acc[2*jp]);
                MUL2(t1, xv[(2*jp+1)^kk], rv[kk]);
                FMA2(acc[2*jp+1], cB, t1, acc[2*jp+1]);
            }
        }
    }
    __syncthreads();
    float* Os = sm;   // 64 rows x 68 floats, reuses Cs2 region
    #pragma unroll
    for (int jj = 0; jj < 8; jj++) {
        float lo, hi; UNPACK2(lo, hi, acc[jj]);
        int sjq = sjb[jo*8 + jj];
        Os[(2*lane)*68 + sjq]   = lo;
        Os[(2*lane+1)*68 + sjq] = hi;
    }
    __syncthreads();
    #pragma unroll
    for (int r = 0; r < 4; r++) {
        int idx = t + 256*r;
        int row = idx >> 4, c4 = idx & 15;
        float4 v = *(const float4*)(Os + row*68 + c4*4);
        *(float4*)(out + (size_t)(bg*64 + row)*8192 + (size_t)n*64 + c4*4) = v;
    }
}

// ---------------------------------------------------------------------------
extern "C" void kernel_launch(void* const* d_in, const int* in_sizes, int n_in,
                              void* d_out, int out_size) {
    const float* x      = (const float*)d_in[0];
    const float* w_gp   = (const float*)d_in[1];
    const float* w_lin  = (const float*)d_in[2];
    const float* b_lin  = (const float*)d_in[3];
    const float* a_norm = (const float*)d_in[4];
    const float* cayley = (const float*)d_in[5];
    const int*   pidx   = (const int*)d_in[7];
    int P = in_sizes[7] / 3;
    float* out = (float*)d_out;
    (void)n_in; (void)out_size;

    cudaFuncSetAttribute(k_linear,   cudaFuncAttributeMaxDynamicSharedMemorySize, 25472*4);
    cudaFuncSetAttribute(k_bilinear, cudaFuncAttributeMaxDynamicSharedMemorySize, 16640*4);

    k_setup_tables<<<16, 256>>>(cayley);
    k_setup_coef<<<128, 256>>>(w_gp, pidx, P);
    k_linear<<<1024, 256, 25472*4>>>(x, w_lin, b_lin, a_norm);
    k_bilinear<<<dim3(128, 4), 256, 16640*4>>>(x, out);
}